// round 10
// baseline (speedup 1.0000x reference)
#include <cuda_runtime.h>
#include <cstdint>
#include <math_constants.h>

#define BB   2
#define NN   8192
#define KK   10
#define KS   11            // KK + 1 slot absorbs self
#define G    16
#define NCB  (G * G * G)   // 4096 cells (12-bit Morton)
#define TPB  128
#define WIN  128           // warm window = the block's own queries
#define NCH  128           // chunks per batch (64 points each)

// Scratch (no device allocation allowed)
__device__ float4 g_sortedPts[BB * NN];  // {-2x,-2y,-2z,|p|^2} Morton-sorted
__device__ float4 g_sortedQ[BB * NN];    // q = p1-p2, Morton-sorted
__device__ float4 g_chunkLo[BB * NCH];
__device__ float4 g_chunkHi[BB * NCH];
__device__ float  g_acc;
__device__ unsigned int g_bdone;

__device__ __forceinline__ int cell_coord(float v) {
    float u = normcdff(v);                 // iid N(0,1) -> Uniform(0,1)
    int c = (int)(u * (float)G);
    return min(G - 1, max(0, c));
}

__device__ __forceinline__ int spread4(int v) {
    return (v & 1) | ((v & 2) << 2) | ((v & 4) << 4) | ((v & 8) << 6);
}

// One block (1024 thr) per batch: count -> scan -> scatter -> chunk AABBs.
__global__ __launch_bounds__(1024) void build_kernel(const float* __restrict__ p1,
                                                     const float* __restrict__ p2) {
    __shared__ int scnt[NCB];      // counts, then cursors
    __shared__ int ssum[1024];

    const int b = blockIdx.x;
    const int t = threadIdx.x;
    const long qb = (long)b * NN;

    if (b == 0 && t == 0) { g_acc = 0.0f; g_bdone = 0u; }

    for (int j = t; j < NCB; j += 1024) scnt[j] = 0;
    __syncthreads();

    // count (keep codes in registers for the scatter phase)
    int codes[8];
#pragma unroll
    for (int u = 0; u < 8; ++u) {
        int gi = b * NN + u * 1024 + t;
        float x = p1[3 * gi + 0], y = p1[3 * gi + 1], z = p1[3 * gi + 2];
        int code = spread4(cell_coord(x))
                 | (spread4(cell_coord(y)) << 1)
                 | (spread4(cell_coord(z)) << 2);
        codes[u] = code;
        atomicAdd(&scnt[code], 1);
    }
    __syncthreads();

    // exclusive scan of 4096 counts (4 per thread + Hillis-Steele on 1024)
    int base = t * 4;
    int c0 = scnt[base + 0], c1 = scnt[base + 1];
    int c2 = scnt[base + 2], c3 = scnt[base + 3];
    int s4 = c0 + c1 + c2 + c3;
    ssum[t] = s4;
    __syncthreads();
    for (int off = 1; off < 1024; off <<= 1) {
        int v = (t >= off) ? ssum[t - off] : 0;
        __syncthreads();
        if (t >= off) ssum[t] += v;
        __syncthreads();
    }
    int st = ssum[t] - s4;   // exclusive prefix
    scnt[base + 0] = st;
    scnt[base + 1] = st + c0;
    scnt[base + 2] = st + c0 + c1;
    scnt[base + 3] = st + c0 + c1 + c2;
    __syncthreads();

    // scatter (atomic cursors in smem)
#pragma unroll
    for (int u = 0; u < 8; ++u) {
        int gi = b * NN + u * 1024 + t;
        int pos = atomicAdd(&scnt[codes[u]], 1);
        float x = p1[3 * gi + 0], y = p1[3 * gi + 1], z = p1[3 * gi + 2];
        float a = p2[3 * gi + 0], bb = p2[3 * gi + 1], c = p2[3 * gi + 2];
        float w = fmaf(z, z, fmaf(y, y, x * x));
        g_sortedPts[qb + pos] = make_float4(-2.0f * x, -2.0f * y, -2.0f * z, w);
        g_sortedQ[qb + pos]   = make_float4(x - a, y - bb, z - c, 0.0f);
    }
    __syncthreads();   // block-scope: global writes above visible below

    // chunk AABBs: 32 warps x 4 chunks, 2 points/lane, shuffle reduce
    const int wid = t >> 5, lane = t & 31;
    const unsigned full = 0xffffffffu;
#pragma unroll
    for (int k = 0; k < 4; ++k) {
        int ch = wid * 4 + k;
        float4 pA = g_sortedPts[qb + ch * 64 + lane];
        float4 pB = g_sortedPts[qb + ch * 64 + 32 + lane];
        float ax = -0.5f * pA.x, ay = -0.5f * pA.y, az = -0.5f * pA.z;
        float bx = -0.5f * pB.x, by = -0.5f * pB.y, bz = -0.5f * pB.z;
        float lx = fminf(ax, bx), ly = fminf(ay, by), lz = fminf(az, bz);
        float hx = fmaxf(ax, bx), hy = fmaxf(ay, by), hz = fmaxf(az, bz);
#pragma unroll
        for (int off = 16; off > 0; off >>= 1) {
            lx = fminf(lx, __shfl_xor_sync(full, lx, off));
            ly = fminf(ly, __shfl_xor_sync(full, ly, off));
            lz = fminf(lz, __shfl_xor_sync(full, lz, off));
            hx = fmaxf(hx, __shfl_xor_sync(full, hx, off));
            hy = fmaxf(hy, __shfl_xor_sync(full, hy, off));
            hz = fmaxf(hz, __shfl_xor_sync(full, hz, off));
        }
        if (lane == 0) {
            g_chunkLo[b * NCH + ch] = make_float4(lx, ly, lz, 0.0f);
            g_chunkHi[b * NCH + ch] = make_float4(hx, hy, hz, 0.0f);
        }
    }
}

// Branchless sorted insert into ascending 11-list (value+index).
__device__ __forceinline__ void insert11(float v, int vi,
                                         float* __restrict__ dist,
                                         int* __restrict__ nn) {
    bool p[KS];
#pragma unroll
    for (int k = 0; k < KS; ++k) p[k] = v < dist[k];
#pragma unroll
    for (int k = KS - 1; k >= 1; --k) {
        dist[k] = p[k] ? (p[k - 1] ? dist[k - 1] : v) : dist[k];
        nn[k]   = p[k] ? (p[k - 1] ? nn[k - 1]  : vi) : nn[k];
    }
    dist[0] = p[0] ? v  : dist[0];
    nn[0]   = p[0] ? vi : nn[0];
}

// Distance-only branchless insert.
__device__ __forceinline__ void insertD(float v, float* __restrict__ d) {
    bool p[KS];
#pragma unroll
    for (int k = 0; k < KS; ++k) p[k] = v < d[k];
#pragma unroll
    for (int k = KS - 1; k >= 1; --k)
        d[k] = p[k] ? (p[k - 1] ? d[k - 1] : v) : d[k];
    d[0] = p[0] ? v : d[0];
}

__device__ __forceinline__ float dist2(float4 c, float4 me) {
    return fmaf(c.x, me.x, fmaf(c.y, me.y, fmaf(c.z, me.z, me.w + c.w)));
}

// grid (NN/TPB, BB): one thread per Morton-sorted query.
// Warm threshold + exact chunk culling + fused L1 loss + finalize.
__global__ __launch_bounds__(TPB) void knn_loss_kernel(float* __restrict__ out,
                                                       int nblocks) {
    __shared__ float4 slo[NCH], shi[NCH];
    __shared__ float4 win[WIN];
    __shared__ float  wsum[TPB / 32];

    const unsigned full = 0xffffffffu;
    const int b    = blockIdx.y;
    const int blk0 = blockIdx.x * TPB;
    const int s    = blk0 + threadIdx.x;       // sorted query position
    const long qb  = (long)b * NN;
    const float4* __restrict__ cand = g_sortedPts + qb;

    for (int j = threadIdx.x; j < NCH; j += TPB) {
        slo[j] = g_chunkLo[b * NCH + j];
        shi[j] = g_chunkHi[b * NCH + j];
    }
    win[threadIdx.x] = cand[blk0 + threadIdx.x];   // WIN == TPB
    __syncthreads();

    const float4 cb = win[threadIdx.x];
    const float4 me = make_float4(-0.5f * cb.x, -0.5f * cb.y, -0.5f * cb.z, cb.w);

    // ---- Phase A: warm threshold from own block's window (subset => upper bound)
    float dD[KS];
#pragma unroll
    for (int k = 0; k < KS; ++k) dD[k] = CUDART_INF_F;
    for (int j = 0; j < WIN; ++j)
        insertD(dist2(win[j], me), dD);
    const float thr0 = dD[KS - 1];

    // ---- Phase B: chunk-culled scan
    float dist[KS];
    int   nn[KS];
#pragma unroll
    for (int k = 0; k < KS; ++k) { dist[k] = CUDART_INF_F; nn[k] = -1; }

    for (int c = 0; c < NCH; ++c) {
        float4 lo = slo[c], hi = shi[c];
        float ddx = fmaxf(fmaxf(lo.x - me.x, me.x - hi.x), 0.0f);
        float ddy = fmaxf(fmaxf(lo.y - me.y, me.y - hi.y), 0.0f);
        float ddz = fmaxf(fmaxf(lo.z - me.z, me.z - hi.z), 0.0f);
        float d2box = fmaf(ddx, ddx, fmaf(ddy, ddy, ddz * ddz));
        float thrc  = fminf(thr0, dist[KS - 1]);
        if (__any_sync(full, d2box <= thrc + 1e-5f)) {   // eps: formula-rounding margin
            const float4* __restrict__ cp = cand + c * 64;
            for (int j0 = 0; j0 < 64; j0 += 8) {
                float d2v[8];
#pragma unroll
                for (int u = 0; u < 8; ++u)
                    d2v[u] = dist2(__ldg(cp + j0 + u), me);
                float mn = fminf(fminf(fminf(d2v[0], d2v[1]), fminf(d2v[2], d2v[3])),
                                 fminf(fminf(d2v[4], d2v[5]), fminf(d2v[6], d2v[7])));
                float thrv = fminf(thr0, dist[KS - 1]);
                if (__any_sync(full, mn <= thrv)) {
#pragma unroll
                    for (int u = 0; u < 8; ++u) {
                        bool p = d2v[u] <= thrv;
                        if (__any_sync(full, p)) {
                            float v = p ? d2v[u] : CUDART_INF_F;
                            insert11(v, c * 64 + j0 + u, dist, nn);
                        }
                    }
                }
            }
        }
    }

    // ---- Epilogue: lap1-lap2 = mean_k q[nbr] - q_self (self = sorted pos s)
    const float4* __restrict__ qv = g_sortedQ + qb;
    float sx = 0.0f, sy = 0.0f, sz = 0.0f;
#pragma unroll
    for (int k = 0; k < KS; ++k) {
        int j = nn[k];
        if (j != s && j >= 0) {
            float4 v = __ldg(&qv[j]);
            sx += v.x; sy += v.y; sz += v.z;
        }
    }
    float4 myq = qv[s];
    const float inv_k = 1.0f / (float)KK;
    float lx = sx * inv_k - myq.x;
    float ly = sy * inv_k - myq.y;
    float lz = sz * inv_k - myq.z;
    float contrib = fabsf(lx) + fabsf(ly) + fabsf(lz);

#pragma unroll
    for (int off = 16; off > 0; off >>= 1)
        contrib += __shfl_down_sync(full, contrib, off);
    if ((threadIdx.x & 31) == 0) wsum[threadIdx.x >> 5] = contrib;
    __syncthreads();
    if (threadIdx.x == 0) {
        float ssum2 = 0.0f;
#pragma unroll
        for (int w = 0; w < TPB / 32; ++w) ssum2 += wsum[w];
        atomicAdd(&g_acc, ssum2);
        __threadfence();
        unsigned int done = atomicAdd(&g_bdone, 1u);
        if (done == (unsigned int)(nblocks - 1)) {
            float acc = *((volatile float*)&g_acc);
            out[0] = acc * (1.0f / (float)(BB * NN * 3));
        }
    }
}

extern "C" void kernel_launch(void* const* d_in, const int* in_sizes, int n_in,
                              void* d_out, int out_size) {
    const float* p1 = (const float*)d_in[0];
    const float* p2 = (const float*)d_in[1];
    float* out = (float*)d_out;

    build_kernel<<<BB, 1024>>>(p1, p2);
    dim3 grid(NN / TPB, BB);
    knn_loss_kernel<<<grid, TPB>>>(out, (NN / TPB) * BB);
}

// round 13
// speedup vs baseline: 1.0385x; 1.0385x over previous
#include <cuda_runtime.h>
#include <cstdint>
#include <math_constants.h>

#define BB   2
#define NN   8192
#define KK   10
#define KS   11            // KK + 1 slot absorbs self
#define G    16
#define NCB  (G * G * G)   // 4096 cells (12-bit Morton)
#define TPB  128
#define NCH  128           // chunks per batch (64 points each); == TPB
#define MAXC 32            // chunks per smem wave

// Scratch (no device allocation allowed)
__device__ float4 g_sortedPts[BB * NN];  // {-2x,-2y,-2z,|p|^2} Morton-sorted
__device__ float4 g_sortedQ[BB * NN];    // q = p1-p2, Morton-sorted
__device__ float4 g_chunkLo[BB * NCH];
__device__ float4 g_chunkHi[BB * NCH];
__device__ float  g_acc;
__device__ unsigned int g_bdone;

__device__ __forceinline__ int cell_coord(float v) {
    float u = normcdff(v);                 // iid N(0,1) -> Uniform(0,1)
    int c = (int)(u * (float)G);
    return min(G - 1, max(0, c));
}

__device__ __forceinline__ int spread4(int v) {
    return (v & 1) | ((v & 2) << 2) | ((v & 4) << 4) | ((v & 8) << 6);
}

// One block (1024 thr) per batch: count -> scan -> scatter -> chunk AABBs.
__global__ __launch_bounds__(1024) void build_kernel(const float* __restrict__ p1,
                                                     const float* __restrict__ p2) {
    __shared__ int scnt[NCB];      // counts, then cursors
    __shared__ int swp[32];

    const int b = blockIdx.x;
    const int t = threadIdx.x;
    const int lane = t & 31, wid = t >> 5;
    const unsigned full = 0xffffffffu;
    const long qb = (long)b * NN;

    if (b == 0 && t == 0) { g_acc = 0.0f; g_bdone = 0u; }

    for (int j = t; j < NCB; j += 1024) scnt[j] = 0;
    __syncthreads();

    // count (keep codes in registers for the scatter phase)
    int codes[8];
#pragma unroll
    for (int u = 0; u < 8; ++u) {
        int gi = b * NN + u * 1024 + t;
        float x = p1[3 * gi + 0], y = p1[3 * gi + 1], z = p1[3 * gi + 2];
        int code = spread4(cell_coord(x))
                 | (spread4(cell_coord(y)) << 1)
                 | (spread4(cell_coord(z)) << 2);
        codes[u] = code;
        atomicAdd(&scnt[code], 1);
    }
    __syncthreads();

    // exclusive scan of 4096 counts: 4/thread + shuffle scan over 1024 threads
    int base = t * 4;
    int c0 = scnt[base + 0], c1 = scnt[base + 1];
    int c2 = scnt[base + 2], c3 = scnt[base + 3];
    int s4 = c0 + c1 + c2 + c3;
    int v = s4;
#pragma unroll
    for (int off = 1; off < 32; off <<= 1) {
        int n = __shfl_up_sync(full, v, off);
        if (lane >= off) v += n;
    }
    if (lane == 31) swp[wid] = v;
    __syncthreads();
    if (wid == 0) {
        int w = swp[lane];
#pragma unroll
        for (int off = 1; off < 32; off <<= 1) {
            int n = __shfl_up_sync(full, w, off);
            if (lane >= off) w += n;
        }
        swp[lane] = w;
    }
    __syncthreads();
    int st = ((wid > 0) ? swp[wid - 1] : 0) + v - s4;   // exclusive prefix
    scnt[base + 0] = st;
    scnt[base + 1] = st + c0;
    scnt[base + 2] = st + c0 + c1;
    scnt[base + 3] = st + c0 + c1 + c2;
    __syncthreads();

    // scatter (atomic cursors in smem)
#pragma unroll
    for (int u = 0; u < 8; ++u) {
        int gi = b * NN + u * 1024 + t;
        int pos = atomicAdd(&scnt[codes[u]], 1);
        float x = p1[3 * gi + 0], y = p1[3 * gi + 1], z = p1[3 * gi + 2];
        float a = p2[3 * gi + 0], bb = p2[3 * gi + 1], c = p2[3 * gi + 2];
        float w = fmaf(z, z, fmaf(y, y, x * x));
        g_sortedPts[qb + pos] = make_float4(-2.0f * x, -2.0f * y, -2.0f * z, w);
        g_sortedQ[qb + pos]   = make_float4(x - a, y - bb, z - c, 0.0f);
    }
    __syncthreads();   // block-scope: global writes above visible below

    // chunk AABBs: 32 warps x 4 chunks, 2 points/lane, shuffle reduce
#pragma unroll
    for (int k = 0; k < 4; ++k) {
        int ch = wid * 4 + k;
        float4 pA = g_sortedPts[qb + ch * 64 + lane];
        float4 pB = g_sortedPts[qb + ch * 64 + 32 + lane];
        float ax = -0.5f * pA.x, ay = -0.5f * pA.y, az = -0.5f * pA.z;
        float bx = -0.5f * pB.x, by = -0.5f * pB.y, bz = -0.5f * pB.z;
        float lx = fminf(ax, bx), ly = fminf(ay, by), lz = fminf(az, bz);
        float hx = fmaxf(ax, bx), hy = fmaxf(ay, by), hz = fmaxf(az, bz);
#pragma unroll
        for (int off = 16; off > 0; off >>= 1) {
            lx = fminf(lx, __shfl_xor_sync(full, lx, off));
            ly = fminf(ly, __shfl_xor_sync(full, ly, off));
            lz = fminf(lz, __shfl_xor_sync(full, lz, off));
            hx = fmaxf(hx, __shfl_xor_sync(full, hx, off));
            hy = fmaxf(hy, __shfl_xor_sync(full, hy, off));
            hz = fmaxf(hz, __shfl_xor_sync(full, hz, off));
        }
        if (lane == 0) {
            g_chunkLo[b * NCH + ch] = make_float4(lx, ly, lz, 0.0f);
            g_chunkHi[b * NCH + ch] = make_float4(hx, hy, hz, 0.0f);
        }
    }
}

// Branchless sorted insert into ascending 11-list (value+index).
__device__ __forceinline__ void insert11(float v, int vi,
                                         float* __restrict__ dist,
                                         int* __restrict__ nn) {
    bool p[KS];
#pragma unroll
    for (int k = 0; k < KS; ++k) p[k] = v < dist[k];
#pragma unroll
    for (int k = KS - 1; k >= 1; --k) {
        dist[k] = p[k] ? (p[k - 1] ? dist[k - 1] : v) : dist[k];
        nn[k]   = p[k] ? (p[k - 1] ? nn[k - 1]  : vi) : nn[k];
    }
    dist[0] = p[0] ? v  : dist[0];
    nn[0]   = p[0] ? vi : nn[0];
}

// Distance-only branchless insert.
__device__ __forceinline__ void insertD(float v, float* __restrict__ d) {
    bool p[KS];
#pragma unroll
    for (int k = 0; k < KS; ++k) p[k] = v < d[k];
#pragma unroll
    for (int k = KS - 1; k >= 1; --k)
        d[k] = p[k] ? (p[k - 1] ? d[k - 1] : v) : d[k];
    d[0] = p[0] ? v : d[0];
}

__device__ __forceinline__ float dist2(float4 c, float4 me) {
    return fmaf(c.x, me.x, fmaf(c.y, me.y, fmaf(c.z, me.z, me.w + c.w)));
}

// grid (NN/TPB, BB): one thread per Morton-sorted query.
// Warm threshold -> block-uniform chunk compaction -> dense smem scan.
__global__ __launch_bounds__(TPB) void knn_loss_kernel(float* __restrict__ out,
                                                       int nblocks) {
    __shared__ float4 win[TPB];
    __shared__ float4 tile[MAXC * 64];
    __shared__ int    sacc[NCH];
    __shared__ int    scid[MAXC];
    __shared__ int    swoff[TPB / 32];
    __shared__ float  sred[TPB / 32][8];   // per-warp {lx,ly,lz,hx,hy,hz,thr,loss}

    const unsigned full = 0xffffffffu;
    const int b    = blockIdx.y;
    const int blk0 = blockIdx.x * TPB;
    const int t    = threadIdx.x;
    const int lane = t & 31, wid = t >> 5;
    const int s    = blk0 + t;                 // sorted query position
    const long qb  = (long)b * NN;
    const float4* __restrict__ cand = g_sortedPts + qb;

    win[t] = cand[s];
    __syncthreads();

    const float4 cb = win[t];
    const float4 me = make_float4(-0.5f * cb.x, -0.5f * cb.y, -0.5f * cb.z, cb.w);

    // ---- Phase A: warm threshold from own block's window (subset => upper bound)
    float dD[KS];
#pragma unroll
    for (int k = 0; k < KS; ++k) dD[k] = CUDART_INF_F;
    for (int j = 0; j < TPB; ++j)
        insertD(dist2(win[j], me), dD);
    const float thr0 = dD[KS - 1];

    // ---- Block AABB of queries + thrmax (warp shuffles, then smem combine)
    {
        float lx = me.x, ly = me.y, lz = me.z;
        float hx = me.x, hy = me.y, hz = me.z;
        float th = thr0;
#pragma unroll
        for (int off = 16; off > 0; off >>= 1) {
            lx = fminf(lx, __shfl_xor_sync(full, lx, off));
            ly = fminf(ly, __shfl_xor_sync(full, ly, off));
            lz = fminf(lz, __shfl_xor_sync(full, lz, off));
            hx = fmaxf(hx, __shfl_xor_sync(full, hx, off));
            hy = fmaxf(hy, __shfl_xor_sync(full, hy, off));
            hz = fmaxf(hz, __shfl_xor_sync(full, hz, off));
            th = fmaxf(th, __shfl_xor_sync(full, th, off));
        }
        if (lane == 0) {
            sred[wid][0] = lx; sred[wid][1] = ly; sred[wid][2] = lz;
            sred[wid][3] = hx; sred[wid][4] = hy; sred[wid][5] = hz;
            sred[wid][6] = th;
        }
    }
    __syncthreads();
    float blx = fminf(fminf(sred[0][0], sred[1][0]), fminf(sred[2][0], sred[3][0]));
    float bly = fminf(fminf(sred[0][1], sred[1][1]), fminf(sred[2][1], sred[3][1]));
    float blz = fminf(fminf(sred[0][2], sred[1][2]), fminf(sred[2][2], sred[3][2]));
    float bhx = fmaxf(fmaxf(sred[0][3], sred[1][3]), fmaxf(sred[2][3], sred[3][3]));
    float bhy = fmaxf(fmaxf(sred[0][4], sred[1][4]), fmaxf(sred[2][4], sred[3][4]));
    float bhz = fmaxf(fmaxf(sred[0][5], sred[1][5]), fmaxf(sred[2][5], sred[3][5]));
    float thrmax = fmaxf(fmaxf(sred[0][6], sred[1][6]), fmaxf(sred[2][6], sred[3][6]));

    // ---- Chunk accept test: thread t tests chunk t (NCH == TPB). Exact:
    // gap^2(blockAABB, chunkAABB) lower-bounds every member distance.
    bool acc;
    {
        float4 lo = g_chunkLo[b * NCH + t];
        float4 hi = g_chunkHi[b * NCH + t];
        float gx = fmaxf(fmaxf(lo.x - bhx, blx - hi.x), 0.0f);
        float gy = fmaxf(fmaxf(lo.y - bhy, bly - hi.y), 0.0f);
        float gz = fmaxf(fmaxf(lo.z - bhz, blz - hi.z), 0.0f);
        float g2 = fmaf(gx, gx, fmaf(gy, gy, gz * gz));
        acc = (g2 <= thrmax + 1e-5f);
    }
    unsigned ball = __ballot_sync(full, acc);
    if (lane == 0) swoff[wid] = __popc(ball);
    __syncthreads();
    int preoff = 0;
#pragma unroll
    for (int w = 0; w < TPB / 32; ++w) preoff += (w < wid) ? swoff[w] : 0;
    if (acc) sacc[preoff + __popc(ball & ((1u << lane) - 1u))] = t;
    __syncthreads();
    const int nacc = swoff[0] + swoff[1] + swoff[2] + swoff[3];

    // ---- Phase B: dense scan over accepted chunks, staged in smem waves
    float dist[KS];
    int   nn[KS];
#pragma unroll
    for (int k = 0; k < KS; ++k) { dist[k] = CUDART_INF_F; nn[k] = -1; }

    for (int w0 = 0; w0 < nacc; w0 += MAXC) {
        const int nw = min(MAXC, nacc - w0);
        __syncthreads();   // protect tile reuse
        if (t < nw) scid[t] = sacc[w0 + t];
        for (int j = t; j < nw * 64; j += TPB)
            tile[j] = cand[sacc[w0 + (j >> 6)] * 64 + (j & 63)];
        __syncthreads();

        const int npts = nw * 64;
        for (int j0 = 0; j0 < npts; j0 += 8) {
            float d2v[8];
#pragma unroll
            for (int u = 0; u < 8; ++u)
                d2v[u] = dist2(tile[j0 + u], me);
            float mn = fminf(fminf(fminf(d2v[0], d2v[1]), fminf(d2v[2], d2v[3])),
                             fminf(fminf(d2v[4], d2v[5]), fminf(d2v[6], d2v[7])));
            float thrv = fminf(thr0, dist[KS - 1]);
            if (__any_sync(full, mn <= thrv)) {
                int cbase = scid[j0 >> 6] * 64 + (j0 & 63);
#pragma unroll
                for (int u = 0; u < 8; ++u) {
                    bool p = d2v[u] <= thrv;
                    if (__any_sync(full, p)) {
                        float v = p ? d2v[u] : CUDART_INF_F;
                        insert11(v, cbase + u, dist, nn);
                    }
                }
            }
        }
    }

    // ---- Epilogue: lap1-lap2 = mean_k q[nbr] - q_self (self = sorted pos s)
    const float4* __restrict__ qv = g_sortedQ + qb;
    float sx = 0.0f, sy = 0.0f, sz = 0.0f;
#pragma unroll
    for (int k = 0; k < KS; ++k) {
        int j = nn[k];
        if (j != s && j >= 0) {
            float4 v = __ldg(&qv[j]);
            sx += v.x; sy += v.y; sz += v.z;
        }
    }
    float4 myq = qv[s];
    const float inv_k = 1.0f / (float)KK;
    float lx = sx * inv_k - myq.x;
    float ly = sy * inv_k - myq.y;
    float lz = sz * inv_k - myq.z;
    float contrib = fabsf(lx) + fabsf(ly) + fabsf(lz);

#pragma unroll
    for (int off = 16; off > 0; off >>= 1)
        contrib += __shfl_down_sync(full, contrib, off);
    if (lane == 0) sred[wid][7] = contrib;
    __syncthreads();
    if (t == 0) {
        float ssum2 = sred[0][7] + sred[1][7] + sred[2][7] + sred[3][7];
        atomicAdd(&g_acc, ssum2);
        __threadfence();
        unsigned int done = atomicAdd(&g_bdone, 1u);
        if (done == (unsigned int)(nblocks - 1)) {
            float acc2 = *((volatile float*)&g_acc);
            out[0] = acc2 * (1.0f / (float)(BB * NN * 3));
        }
    }
}

extern "C" void kernel_launch(void* const* d_in, const int* in_sizes, int n_in,
                              void* d_out, int out_size) {
    const float* p1 = (const float*)d_in[0];
    const float* p2 = (const float*)d_in[1];
    float* out = (float*)d_out;

    build_kernel<<<BB, 1024>>>(p1, p2);
    dim3 grid(NN / TPB, BB);
    knn_loss_kernel<<<grid, TPB>>>(out, (NN / TPB) * BB);
}

// round 16
// speedup vs baseline: 1.1432x; 1.1008x over previous
#include <cuda_runtime.h>
#include <cstdint>
#include <math_constants.h>

#define BB   2
#define NN   8192
#define KK   10
#define KS   11            // KK + 1 slot absorbs self
#define G    16
#define NCB  (G * G * G)   // 4096 cells (12-bit Morton)
#define QPW  32            // queries per warp-group (one per lane)
#define REP  4             // replica warps per query group
#define TPB  (QPW * REP)   // 128
#define NCH  128           // chunks per batch (64 points each)

// Scratch (no device allocation allowed)
__device__ float4 g_sortedPts[BB * NN];  // {-2x,-2y,-2z,|p|^2} Morton-sorted
__device__ float4 g_sortedQ[BB * NN];    // q = p1-p2, Morton-sorted
__device__ float4 g_chunkLo[BB * NCH];
__device__ float4 g_chunkHi[BB * NCH];
__device__ float  g_acc;
__device__ unsigned int g_bdone;

__device__ __forceinline__ int cell_coord(float v) {
    float u = normcdff(v);                 // iid N(0,1) -> Uniform(0,1)
    int c = (int)(u * (float)G);
    return min(G - 1, max(0, c));
}

__device__ __forceinline__ int spread4(int v) {
    return (v & 1) | ((v & 2) << 2) | ((v & 4) << 4) | ((v & 8) << 6);
}

// One block (1024 thr) per batch: count -> scan -> scatter -> chunk AABBs.
__global__ __launch_bounds__(1024) void build_kernel(const float* __restrict__ p1,
                                                     const float* __restrict__ p2) {
    __shared__ int scnt[NCB];      // counts, then cursors
    __shared__ int swp[32];

    const int b = blockIdx.x;
    const int t = threadIdx.x;
    const int lane = t & 31, wid = t >> 5;
    const unsigned full = 0xffffffffu;
    const long qb = (long)b * NN;

    if (b == 0 && t == 0) { g_acc = 0.0f; g_bdone = 0u; }

    for (int j = t; j < NCB; j += 1024) scnt[j] = 0;
    __syncthreads();

    int codes[8];
#pragma unroll
    for (int u = 0; u < 8; ++u) {
        int gi = b * NN + u * 1024 + t;
        float x = p1[3 * gi + 0], y = p1[3 * gi + 1], z = p1[3 * gi + 2];
        int code = spread4(cell_coord(x))
                 | (spread4(cell_coord(y)) << 1)
                 | (spread4(cell_coord(z)) << 2);
        codes[u] = code;
        atomicAdd(&scnt[code], 1);
    }
    __syncthreads();

    // exclusive scan of 4096 counts: 4/thread + shuffle scan over 1024 threads
    int base = t * 4;
    int c0 = scnt[base + 0], c1 = scnt[base + 1];
    int c2 = scnt[base + 2], c3 = scnt[base + 3];
    int s4 = c0 + c1 + c2 + c3;
    int v = s4;
#pragma unroll
    for (int off = 1; off < 32; off <<= 1) {
        int n = __shfl_up_sync(full, v, off);
        if (lane >= off) v += n;
    }
    if (lane == 31) swp[wid] = v;
    __syncthreads();
    if (wid == 0) {
        int w = swp[lane];
#pragma unroll
        for (int off = 1; off < 32; off <<= 1) {
            int n = __shfl_up_sync(full, w, off);
            if (lane >= off) w += n;
        }
        swp[lane] = w;
    }
    __syncthreads();
    int st = ((wid > 0) ? swp[wid - 1] : 0) + v - s4;
    scnt[base + 0] = st;
    scnt[base + 1] = st + c0;
    scnt[base + 2] = st + c0 + c1;
    scnt[base + 3] = st + c0 + c1 + c2;
    __syncthreads();

#pragma unroll
    for (int u = 0; u < 8; ++u) {
        int gi = b * NN + u * 1024 + t;
        int pos = atomicAdd(&scnt[codes[u]], 1);
        float x = p1[3 * gi + 0], y = p1[3 * gi + 1], z = p1[3 * gi + 2];
        float a = p2[3 * gi + 0], bb = p2[3 * gi + 1], c = p2[3 * gi + 2];
        float w = fmaf(z, z, fmaf(y, y, x * x));
        g_sortedPts[qb + pos] = make_float4(-2.0f * x, -2.0f * y, -2.0f * z, w);
        g_sortedQ[qb + pos]   = make_float4(x - a, y - bb, z - c, 0.0f);
    }
    __syncthreads();

    // chunk AABBs: 32 warps x 4 chunks, 2 points/lane, shuffle reduce
#pragma unroll
    for (int k = 0; k < 4; ++k) {
        int ch = wid * 4 + k;
        float4 pA = g_sortedPts[qb + ch * 64 + lane];
        float4 pB = g_sortedPts[qb + ch * 64 + 32 + lane];
        float ax = -0.5f * pA.x, ay = -0.5f * pA.y, az = -0.5f * pA.z;
        float bx = -0.5f * pB.x, by = -0.5f * pB.y, bz = -0.5f * pB.z;
        float lx = fminf(ax, bx), ly = fminf(ay, by), lz = fminf(az, bz);
        float hx = fmaxf(ax, bx), hy = fmaxf(ay, by), hz = fmaxf(az, bz);
#pragma unroll
        for (int off = 16; off > 0; off >>= 1) {
            lx = fminf(lx, __shfl_xor_sync(full, lx, off));
            ly = fminf(ly, __shfl_xor_sync(full, ly, off));
            lz = fminf(lz, __shfl_xor_sync(full, lz, off));
            hx = fmaxf(hx, __shfl_xor_sync(full, hx, off));
            hy = fmaxf(hy, __shfl_xor_sync(full, hy, off));
            hz = fmaxf(hz, __shfl_xor_sync(full, hz, off));
        }
        if (lane == 0) {
            g_chunkLo[b * NCH + ch] = make_float4(lx, ly, lz, 0.0f);
            g_chunkHi[b * NCH + ch] = make_float4(hx, hy, hz, 0.0f);
        }
    }
}

// Branchless sorted insert into ascending 11-list (value+index).
__device__ __forceinline__ void insert11(float v, int vi,
                                         float* __restrict__ dist,
                                         int* __restrict__ nn) {
    bool p[KS];
#pragma unroll
    for (int k = 0; k < KS; ++k) p[k] = v < dist[k];
#pragma unroll
    for (int k = KS - 1; k >= 1; --k) {
        dist[k] = p[k] ? (p[k - 1] ? dist[k - 1] : v) : dist[k];
        nn[k]   = p[k] ? (p[k - 1] ? nn[k - 1]  : vi) : nn[k];
    }
    dist[0] = p[0] ? v  : dist[0];
    nn[0]   = p[0] ? vi : nn[0];
}

// Distance-only branchless insert.
__device__ __forceinline__ void insertD(float v, float* __restrict__ d) {
    bool p[KS];
#pragma unroll
    for (int k = 0; k < KS; ++k) p[k] = v < d[k];
#pragma unroll
    for (int k = KS - 1; k >= 1; --k)
        d[k] = p[k] ? (p[k - 1] ? d[k - 1] : v) : d[k];
    d[0] = p[0] ? v : d[0];
}

__device__ __forceinline__ float dist2(float4 c, float4 me) {
    return fmaf(c.x, me.x, fmaf(c.y, me.y, fmaf(c.z, me.z, me.w + c.w)));
}

// grid (NN/QPW, BB): 32 queries per block, 4 replica warps split the chunks.
__global__ __launch_bounds__(TPB) void knn_loss_kernel(float* __restrict__ out,
                                                       int nblocks) {
    __shared__ float4 win[128];
    __shared__ int    sacc[NCH];
    __shared__ int    snacc;
    __shared__ float  sd[REP][QPW][KS];
    __shared__ int    si[REP][QPW][KS];

    const unsigned full = 0xffffffffu;
    const int b    = blockIdx.y;
    const int q0   = blockIdx.x * QPW;
    const int t    = threadIdx.x;
    const int lane = t & 31;
    const int w    = t >> 5;                   // replica id
    const long qb  = (long)b * NN;
    const float4* __restrict__ cand = g_sortedPts + qb;

    const int wb = q0 & ~127;                  // 128-aligned window base
    win[t] = cand[wb + t];
    __syncthreads();

    const int s = q0 + lane;                   // own query sorted position
    const float4 cb = win[s - wb];
    const float4 me = make_float4(-0.5f * cb.x, -0.5f * cb.y, -0.5f * cb.z, cb.w);

    // ---- Phase A: warm threshold over the 128-point window (upper bound)
    float dD[KS];
#pragma unroll
    for (int k = 0; k < KS; ++k) dD[k] = CUDART_INF_F;
    for (int j = 0; j < 128; ++j) {
        float d2 = dist2(win[j], me);
        if (d2 < dD[KS - 1]) insertD(d2, dD);  // guarded: predication only
    }
    const float thr0 = dD[KS - 1];

    // ---- Warp AABB of its 32 queries + thrmax (identical in all replicas)
    float blx = me.x, bly = me.y, blz = me.z;
    float bhx = me.x, bhy = me.y, bhz = me.z;
    float thrmax = thr0;
#pragma unroll
    for (int off = 16; off > 0; off >>= 1) {
        blx = fminf(blx, __shfl_xor_sync(full, blx, off));
        bly = fminf(bly, __shfl_xor_sync(full, bly, off));
        blz = fminf(blz, __shfl_xor_sync(full, blz, off));
        bhx = fmaxf(bhx, __shfl_xor_sync(full, bhx, off));
        bhy = fmaxf(bhy, __shfl_xor_sync(full, bhy, off));
        bhz = fmaxf(bhz, __shfl_xor_sync(full, bhz, off));
        thrmax = fmaxf(thrmax, __shfl_xor_sync(full, thrmax, off));
    }

    // ---- Chunk accept + compact (warp 0 only; exact lower-bound test)
    if (w == 0) {
        int base = 0;
#pragma unroll
        for (int g = 0; g < NCH / 32; ++g) {
            int c = g * 32 + lane;
            float4 lo = __ldg(&g_chunkLo[b * NCH + c]);
            float4 hi = __ldg(&g_chunkHi[b * NCH + c]);
            float gx = fmaxf(fmaxf(lo.x - bhx, blx - hi.x), 0.0f);
            float gy = fmaxf(fmaxf(lo.y - bhy, bly - hi.y), 0.0f);
            float gz = fmaxf(fmaxf(lo.z - bhz, blz - hi.z), 0.0f);
            float g2 = fmaf(gx, gx, fmaf(gy, gy, gz * gz));
            bool acc = (g2 <= thrmax + 1e-5f);
            unsigned ball = __ballot_sync(full, acc);
            if (acc) sacc[base + __popc(ball & ((1u << lane) - 1u))] = c;
            base += __popc(ball);
        }
        if (lane == 0) snacc = base;
    }
    __syncthreads();
    const int nacc = snacc;

    // ---- Phase B: replica w scans chunks sacc[w], sacc[w+REP], ...
    float dist[KS];
    int   nn[KS];
#pragma unroll
    for (int k = 0; k < KS; ++k) { dist[k] = CUDART_INF_F; nn[k] = -1; }

    for (int ci = w; ci < nacc; ci += REP) {
        const int c = sacc[ci];
        const float4* __restrict__ cp = cand + c * 64;
        for (int j0 = 0; j0 < 64; j0 += 8) {
            float d2v[8];
#pragma unroll
            for (int u = 0; u < 8; ++u)
                d2v[u] = dist2(__ldg(cp + j0 + u), me);
            float mn = fminf(fminf(fminf(d2v[0], d2v[1]), fminf(d2v[2], d2v[3])),
                             fminf(fminf(d2v[4], d2v[5]), fminf(d2v[6], d2v[7])));
            float thrv = fminf(thr0, dist[KS - 1]);
            if (__any_sync(full, mn <= thrv)) {
#pragma unroll
                for (int u = 0; u < 8; ++u) {
                    bool p = d2v[u] <= thrv;
                    if (__any_sync(full, p)) {
                        float v = p ? d2v[u] : CUDART_INF_F;
                        insert11(v, c * 64 + j0 + u, dist, nn);
                    }
                }
            }
        }
    }

#pragma unroll
    for (int k = 0; k < KS; ++k) {
        sd[w][lane][k] = dist[k];
        si[w][lane][k] = nn[k];
    }
    __syncthreads();

    // ---- Merge 4 sorted lists + loss (warp 0; lane = its query)
    if (w == 0) {
        int p0 = 0, p1 = 0, p2 = 0, p3 = 0;
        const float4* __restrict__ qv = g_sortedQ + qb;
        float sx = 0.0f, sy = 0.0f, sz = 0.0f;
        int cnt = 0;
#pragma unroll
        for (int step = 0; step < KS; ++step) {   // first 11 merged entries
            float d0 = sd[0][lane][p0], d1 = sd[1][lane][p1];
            float d2m = sd[2][lane][p2], d3 = sd[3][lane][p3];
            int r = 0; float bd = d0;
            if (d1 < bd) { bd = d1; r = 1; }
            if (d2m < bd) { bd = d2m; r = 2; }
            if (d3 < bd) { bd = d3; r = 3; }
            int idx;
            if (r == 0) { idx = si[0][lane][p0]; ++p0; }
            else if (r == 1) { idx = si[1][lane][p1]; ++p1; }
            else if (r == 2) { idx = si[2][lane][p2]; ++p2; }
            else { idx = si[3][lane][p3]; ++p3; }
            if (idx != s && idx >= 0 && cnt < KK) {
                float4 vq = __ldg(&qv[idx]);
                sx += vq.x; sy += vq.y; sz += vq.z;
                ++cnt;
            }
        }

        float4 myq = __ldg(&qv[s]);
        const float inv_k = 1.0f / (float)KK;
        float lx = sx * inv_k - myq.x;
        float ly = sy * inv_k - myq.y;
        float lz = sz * inv_k - myq.z;
        float contrib = fabsf(lx) + fabsf(ly) + fabsf(lz);

#pragma unroll
        for (int off = 16; off > 0; off >>= 1)
            contrib += __shfl_down_sync(full, contrib, off);
        if (lane == 0) {
            atomicAdd(&g_acc, contrib);
            __threadfence();
            unsigned int done = atomicAdd(&g_bdone, 1u);
            if (done == (unsigned int)(nblocks - 1)) {
                float acc2 = *((volatile float*)&g_acc);
                out[0] = acc2 * (1.0f / (float)(BB * NN * 3));
            }
        }
    }
}

extern "C" void kernel_launch(void* const* d_in, const int* in_sizes, int n_in,
                              void* d_out, int out_size) {
    const float* p1 = (const float*)d_in[0];
    const float* p2 = (const float*)d_in[1];
    float* out = (float*)d_out;

    build_kernel<<<BB, 1024>>>(p1, p2);
    dim3 grid(NN / QPW, BB);
    knn_loss_kernel<<<grid, TPB>>>(out, (NN / QPW) * BB);
}